// round 1
// baseline (speedup 1.0000x reference)
#include <cuda_runtime.h>
#include <cstdint>

#define NN 50000
#define NE 800000
#define DD 64

// ---------------- device scratch (no allocation allowed) ----------------
__device__ int   g_cnt[NN];
__device__ int   g_fill[NN];
__device__ int   g_rowptr[NN + 1];
__device__ int   g_srcs[NE];      // src node id, grouped by dst
__device__ int   g_eidx[NE];      // original edge id, grouped by dst
__device__ float g_hneigh[(size_t)NN * 128];
__device__ float g_hn1[(size_t)NN * DD];
__device__ float g_P[(size_t)NN * DD];
__device__ float g_Q[(size_t)NN * DD];

// ---------------- f32x2 packed-FMA helpers (sm_100+) ----------------
static __device__ __forceinline__ unsigned long long pack2(float a, float b) {
    unsigned long long r;
    asm("mov.b64 %0, {%1, %2};" : "=l"(r) : "f"(a), "f"(b));
    return r;
}
static __device__ __forceinline__ float2 unpack2(unsigned long long v) {
    float2 f;
    asm("mov.b64 {%0, %1}, %2;" : "=f"(f.x), "=f"(f.y) : "l"(v));
    return f;
}
static __device__ __forceinline__ void fma2(unsigned long long& d,
                                            unsigned long long a,
                                            unsigned long long b) {
    asm("fma.rn.f32x2 %0, %1, %2, %0;" : "+l"(d) : "l"(a), "l"(b));
}

// ---------------- CSR build ----------------
__global__ void k_zero() {
    int i = blockIdx.x * blockDim.x + threadIdx.x;
    if (i < NN) { g_cnt[i] = 0; g_fill[i] = 0; }
}

__global__ void k_count(const int* __restrict__ dst) {
    int e = blockIdx.x * blockDim.x + threadIdx.x;
    if (e < NE) atomicAdd(&g_cnt[dst[e]], 1);
}

// single-block exclusive scan of g_cnt -> g_rowptr
__global__ void k_scan() {
    __shared__ int part[1024];
    const int C = (NN + 1023) / 1024;
    int t = threadIdx.x;
    int beg = t * C;
    int end = min(beg + C, NN);
    int s = 0;
    for (int i = beg; i < end; i++) s += g_cnt[i];
    part[t] = s;
    __syncthreads();
    for (int off = 1; off < 1024; off <<= 1) {
        int add = (t >= off) ? part[t - off] : 0;
        __syncthreads();
        part[t] += add;
        __syncthreads();
    }
    int run = (t == 0) ? 0 : part[t - 1];
    for (int i = beg; i < end; i++) { g_rowptr[i] = run; run += g_cnt[i]; }
    if (t == 1023) g_rowptr[NN] = part[1023];
}

__global__ void k_fill(const int* __restrict__ src, const int* __restrict__ dst) {
    int e = blockIdx.x * blockDim.x + threadIdx.x;
    if (e < NE) {
        int d = dst[e];
        int p = g_rowptr[d] + atomicAdd(&g_fill[d], 1);
        g_eidx[p] = e;
        g_srcs[p] = src[e];
    }
}

// ---------------- aggregation: one warp per node, mean of [h[src] | h_e] ----
// layer==0: edge features read from efeats via g_eidx.
// layer==1: edge features recomputed inline as relu(P0[src] + Q0[v] + be0).
__global__ __launch_bounds__(256) void k_agg(const float* __restrict__ hn,
                                             const float* __restrict__ ef,
                                             const float* __restrict__ P0,
                                             const float* __restrict__ Q0,
                                             const float* __restrict__ be0,
                                             int layer) {
    int w = (blockIdx.x * 256 + threadIdx.x) >> 5;
    if (w >= NN) return;
    int lane = threadIdx.x & 31;
    int half = lane >> 4;            // 0: node half, 1: edge half
    int c = (lane & 15) << 2;        // column within 64
    int b = g_rowptr[w];
    int e = g_rowptr[w + 1];

    float4 acc = make_float4(0.f, 0.f, 0.f, 0.f);
    float4 qb  = make_float4(0.f, 0.f, 0.f, 0.f);
    if (layer && half) {
        float4 q  = *(const float4*)(Q0 + (size_t)w * 64 + c);
        float4 bb = *(const float4*)(be0 + c);
        qb = make_float4(q.x + bb.x, q.y + bb.y, q.z + bb.z, q.w + bb.w);
    }

    for (int j = b; j < e; j++) {
        int s = g_srcs[j];
        if (half == 0) {
            float4 x = *(const float4*)(hn + (size_t)s * 64 + c);
            acc.x += x.x; acc.y += x.y; acc.z += x.z; acc.w += x.w;
        } else if (layer == 0) {
            int eid = g_eidx[j];
            float4 x = *(const float4*)(ef + (size_t)eid * 64 + c);
            acc.x += x.x; acc.y += x.y; acc.z += x.z; acc.w += x.w;
        } else {
            float4 p = *(const float4*)(P0 + (size_t)s * 64 + c);
            acc.x += fmaxf(p.x + qb.x, 0.f);
            acc.y += fmaxf(p.y + qb.y, 0.f);
            acc.z += fmaxf(p.z + qb.z, 0.f);
            acc.w += fmaxf(p.w + qb.w, 0.f);
        }
    }
    float inv = 1.f / fmaxf((float)(e - b), 1.f);
    float4 o = make_float4(acc.x * inv, acc.y * inv, acc.z * inv, acc.w * inv);
    *(float4*)(g_hneigh + (size_t)w * 128 + half * 64 + c) = o;
}

// ---------------- node apply: out = relu([hn | hneigh] @ wa + ba) ----------
// one thread per node; weights broadcast from smem; packed f32x2 FMAs
__global__ __launch_bounds__(256) void k_apply(const float* __restrict__ hn,
                                               const float* __restrict__ wa,
                                               const float* __restrict__ ba,
                                               float* __restrict__ out) {
    __shared__ float s_w[192 * 64];  // 48 KB
    int tid = threadIdx.x;
    for (int i = tid * 4; i < 192 * 64; i += 256 * 4)
        *(float4*)(s_w + i) = *(const float4*)(wa + i);
    __syncthreads();

    int v = blockIdx.x * 256 + tid;
    bool act = v < NN;

    unsigned long long yacc[32];
#pragma unroll
    for (int m = 0; m < 16; m++) {
        float4 bb = *(const float4*)(ba + m * 4);
        yacc[2 * m]     = pack2(bb.x, bb.y);
        yacc[2 * m + 1] = pack2(bb.z, bb.w);
    }

    const float* xn = hn + (size_t)(act ? v : 0) * 64;
    const float* xg = g_hneigh + (size_t)(act ? v : 0) * 128;

    for (int ch = 0; ch < 24; ch++) {
        float4 a = make_float4(0.f, 0.f, 0.f, 0.f), d = a;
        if (act) {
            const float* p = (ch < 8) ? (xn + ch * 8) : (xg + (ch - 8) * 8);
            a = *(const float4*)p;
            d = *(const float4*)(p + 4);
        }
        float xs[8] = {a.x, a.y, a.z, a.w, d.x, d.y, d.z, d.w};
#pragma unroll
        for (int kk = 0; kk < 8; kk++) {
            unsigned long long xx = pack2(xs[kk], xs[kk]);
            const ulonglong2* wrow = (const ulonglong2*)(s_w + (ch * 8 + kk) * 64);
#pragma unroll
            for (int j = 0; j < 16; j++) {
                ulonglong2 ww = wrow[j];
                fma2(yacc[2 * j], xx, ww.x);
                fma2(yacc[2 * j + 1], xx, ww.y);
            }
        }
    }

    if (act) {
        float* o = out + (size_t)v * 64;
#pragma unroll
        for (int m = 0; m < 16; m++) {
            float2 f0 = unpack2(yacc[2 * m]);
            float2 f1 = unpack2(yacc[2 * m + 1]);
            *(float4*)(o + m * 4) = make_float4(fmaxf(f0.x, 0.f), fmaxf(f0.y, 0.f),
                                                fmaxf(f1.x, 0.f), fmaxf(f1.y, 0.f));
        }
    }
}

// ---------------- per-node edge-weight halves: P = y @ we[0:64], Q = y @ we[64:128]
__global__ __launch_bounds__(256) void k_pq(const float* __restrict__ hy,
                                            const float* __restrict__ we,
                                            float* __restrict__ P,
                                            float* __restrict__ Q) {
    __shared__ float s_w[128 * 64];  // 32 KB
    int tid = threadIdx.x;
    for (int i = tid * 4; i < 128 * 64; i += 256 * 4)
        *(float4*)(s_w + i) = *(const float4*)(we + i);
    __syncthreads();

    int v = blockIdx.x * 256 + tid;
    bool act = v < NN;
    const float* yr = hy + (size_t)(act ? v : 0) * 64;

    for (int pass = 0; pass < 2; pass++) {
        unsigned long long acc[32];
#pragma unroll
        for (int j = 0; j < 32; j++) acc[j] = 0ull;  // bit pattern of (0.f, 0.f)
        const float* wbase = s_w + pass * 64 * 64;
        for (int k0 = 0; k0 < 16; k0++) {
            float4 f = make_float4(0.f, 0.f, 0.f, 0.f);
            if (act) f = *(const float4*)(yr + k0 * 4);
            float xs[4] = {f.x, f.y, f.z, f.w};
#pragma unroll
            for (int kk = 0; kk < 4; kk++) {
                unsigned long long xx = pack2(xs[kk], xs[kk]);
                const ulonglong2* wrow = (const ulonglong2*)(wbase + (k0 * 4 + kk) * 64);
#pragma unroll
                for (int j = 0; j < 16; j++) {
                    ulonglong2 ww = wrow[j];
                    fma2(acc[2 * j], xx, ww.x);
                    fma2(acc[2 * j + 1], xx, ww.y);
                }
            }
        }
        if (act) {
            float* o = (pass ? Q : P) + (size_t)v * 64;
#pragma unroll
            for (int m = 0; m < 16; m++) {
                float2 f0 = unpack2(acc[2 * m]);
                float2 f1 = unpack2(acc[2 * m + 1]);
                *(float4*)(o + m * 4) = make_float4(f0.x, f0.y, f1.x, f1.y);
            }
        }
    }
}

// ---------------- final edge output: relu(P[src] + Q[dst] + be) -------------
__global__ __launch_bounds__(256) void k_edge(const int* __restrict__ src,
                                              const int* __restrict__ dst,
                                              const float* __restrict__ P,
                                              const float* __restrict__ Q,
                                              const float* __restrict__ be,
                                              float* __restrict__ oute) {
    long long g = (long long)blockIdx.x * 256 + threadIdx.x;
    int e = (int)(g >> 4);
    if (e >= NE) return;
    int c = ((int)g & 15) << 2;
    int s = src[e], d = dst[e];
    float4 p = *(const float4*)(P + (size_t)s * 64 + c);
    float4 q = *(const float4*)(Q + (size_t)d * 64 + c);
    float4 b = *(const float4*)(be + c);
    float4 r = make_float4(fmaxf(p.x + q.x + b.x, 0.f), fmaxf(p.y + q.y + b.y, 0.f),
                           fmaxf(p.z + q.z + b.z, 0.f), fmaxf(p.w + q.w + b.w, 0.f));
    *(float4*)(oute + (size_t)e * 64 + c) = r;
}

// ---------------- launch ----------------
extern "C" void kernel_launch(void* const* d_in, const int* in_sizes, int n_in,
                              void* d_out, int out_size) {
    const float* nf  = (const float*)d_in[0];
    const float* ef  = (const float*)d_in[1];
    const int*   src = (const int*)d_in[2];
    const int*   dst = (const int*)d_in[3];
    const float* wa0 = (const float*)d_in[4];
    const float* ba0 = (const float*)d_in[5];
    const float* we0 = (const float*)d_in[6];
    const float* be0 = (const float*)d_in[7];
    const float* wa1 = (const float*)d_in[8];
    const float* ba1 = (const float*)d_in[9];
    const float* we1 = (const float*)d_in[10];
    const float* be1 = (const float*)d_in[11];

    float* out_n = (float*)d_out;                       // [NN, 64]
    float* out_e = out_n + (size_t)NN * DD;             // [NE, 64]

    float *hn1, *P, *Q;
    cudaGetSymbolAddress((void**)&hn1, g_hn1);
    cudaGetSymbolAddress((void**)&P, g_P);
    cudaGetSymbolAddress((void**)&Q, g_Q);

    // CSR build (graph shared by both layers)
    k_zero<<<(NN + 255) / 256, 256>>>();
    k_count<<<(NE + 255) / 256, 256>>>(dst);
    k_scan<<<1, 1024>>>();
    k_fill<<<(NE + 255) / 256, 256>>>(src, dst);

    // layer 1
    k_agg<<<(NN + 7) / 8, 256>>>(nf, ef, nullptr, nullptr, nullptr, 0);
    k_apply<<<(NN + 255) / 256, 256>>>(nf, wa0, ba0, hn1);
    k_pq<<<(NN + 255) / 256, 256>>>(hn1, we0, P, Q);

    // layer 2 (h_e1 never materialized: recomputed inside k_agg)
    k_agg<<<(NN + 7) / 8, 256>>>(hn1, nullptr, P, Q, be0, 1);
    k_apply<<<(NN + 255) / 256, 256>>>(hn1, wa1, ba1, out_n);
    k_pq<<<(NN + 255) / 256, 256>>>(out_n, we1, P, Q);

    // final edge features straight into d_out
    k_edge<<<((long long)NE * 16 + 255) / 256, 256>>>(src, dst, P, Q, be1, out_e);
}

// round 2
// speedup vs baseline: 1.0780x; 1.0780x over previous
#include <cuda_runtime.h>
#include <cstdint>

#define NN 50000
#define NE 800000
#define DD 64

// ---------------- device scratch (no allocation allowed) ----------------
__device__ int   g_cnt[NN];
__device__ int   g_fill[NN];
__device__ int   g_rowptr[NN + 1];
__device__ int   g_srcs[NE];      // src node id, grouped by dst
__device__ int   g_eidx[NE];      // original edge id, grouped by dst
__device__ float g_hneigh[(size_t)NN * 128];
__device__ float g_hn1[(size_t)NN * DD];
__device__ float g_P[(size_t)NN * DD];
__device__ float g_Q[(size_t)NN * DD];

// ---------------- f32x2 packed-FMA helpers (sm_100+) ----------------
static __device__ __forceinline__ unsigned long long pack2(float a, float b) {
    unsigned long long r;
    asm("mov.b64 %0, {%1, %2};" : "=l"(r) : "f"(a), "f"(b));
    return r;
}
static __device__ __forceinline__ float2 unpack2(unsigned long long v) {
    float2 f;
    asm("mov.b64 {%0, %1}, %2;" : "=f"(f.x), "=f"(f.y) : "l"(v));
    return f;
}
static __device__ __forceinline__ void fma2(unsigned long long& d,
                                            unsigned long long a,
                                            unsigned long long b) {
    asm("fma.rn.f32x2 %0, %1, %2, %0;" : "+l"(d) : "l"(a), "l"(b));
}

static __device__ __forceinline__ float4 relu_add(float4 x, float4 q) {
    return make_float4(fmaxf(x.x + q.x, 0.f), fmaxf(x.y + q.y, 0.f),
                       fmaxf(x.z + q.z, 0.f), fmaxf(x.w + q.w, 0.f));
}

// ---------------- CSR build ----------------
__global__ void k_zero() {
    int i = blockIdx.x * blockDim.x + threadIdx.x;
    if (i < NN) { g_cnt[i] = 0; g_fill[i] = 0; }
}

__global__ void k_count(const int* __restrict__ dst) {
    int e = blockIdx.x * blockDim.x + threadIdx.x;
    if (e < NE) atomicAdd(&g_cnt[dst[e]], 1);
}

// single-block exclusive scan of g_cnt -> g_rowptr
__global__ void k_scan() {
    __shared__ int part[1024];
    const int C = (NN + 1023) / 1024;
    int t = threadIdx.x;
    int beg = t * C;
    int end = min(beg + C, NN);
    int s = 0;
    for (int i = beg; i < end; i++) s += g_cnt[i];
    part[t] = s;
    __syncthreads();
    for (int off = 1; off < 1024; off <<= 1) {
        int add = (t >= off) ? part[t - off] : 0;
        __syncthreads();
        part[t] += add;
        __syncthreads();
    }
    int run = (t == 0) ? 0 : part[t - 1];
    for (int i = beg; i < end; i++) { g_rowptr[i] = run; run += g_cnt[i]; }
    if (t == 1023) g_rowptr[NN] = part[1023];
}

__global__ void k_fill(const int* __restrict__ src, const int* __restrict__ dst) {
    int e = blockIdx.x * blockDim.x + threadIdx.x;
    if (e < NE) {
        int d = dst[e];
        int p = g_rowptr[d] + atomicAdd(&g_fill[d], 1);
        g_eidx[p] = e;
        g_srcs[p] = src[e];
    }
}

// ---------------- aggregation: one warp per node, mean of [h[src] | h_e] ----
// LAYER==0: edge half reads efeats via g_eidx.
// LAYER==1: edge half recomputes h_e1 = relu(P0[src] + Q0[v] + be0) inline.
// Non-divergent main loop: lanes differ only in base pointer / index array.
template <int LAYER>
__global__ __launch_bounds__(256) void k_agg(const float* __restrict__ hn,
                                             const float* __restrict__ ef,
                                             const float* __restrict__ P0,
                                             const float* __restrict__ Q0,
                                             const float* __restrict__ be0) {
    int w = (blockIdx.x * 256 + threadIdx.x) >> 5;
    if (w >= NN) return;
    const int lane = threadIdx.x & 31;
    const int half = lane >> 4;          // 0: node half, 1: edge half
    const int c = (lane & 15) << 2;      // column within 64
    const int b = g_rowptr[w];
    const int e = g_rowptr[w + 1];

    const int* ia = (LAYER == 0 && half) ? g_eidx : g_srcs;
    const float* tb = half ? (LAYER ? P0 : ef) : hn;

    float4 qb = make_float4(0.f, 0.f, 0.f, 0.f);
    if (LAYER && half) {
        float4 q  = *(const float4*)(Q0 + (size_t)w * 64 + c);
        float4 bb = *(const float4*)(be0 + c);
        qb = make_float4(q.x + bb.x, q.y + bb.y, q.z + bb.z, q.w + bb.w);
    }

    float4 acc = make_float4(0.f, 0.f, 0.f, 0.f);
    int j = b;
    for (; j + 4 <= e; j += 4) {
        int s0 = ia[j], s1 = ia[j + 1], s2 = ia[j + 2], s3 = ia[j + 3];
        float4 x0 = __ldg((const float4*)(tb + (size_t)s0 * 64 + c));
        float4 x1 = __ldg((const float4*)(tb + (size_t)s1 * 64 + c));
        float4 x2 = __ldg((const float4*)(tb + (size_t)s2 * 64 + c));
        float4 x3 = __ldg((const float4*)(tb + (size_t)s3 * 64 + c));
        if (LAYER && half) {
            x0 = relu_add(x0, qb); x1 = relu_add(x1, qb);
            x2 = relu_add(x2, qb); x3 = relu_add(x3, qb);
        }
        acc.x += (x0.x + x1.x) + (x2.x + x3.x);
        acc.y += (x0.y + x1.y) + (x2.y + x3.y);
        acc.z += (x0.z + x1.z) + (x2.z + x3.z);
        acc.w += (x0.w + x1.w) + (x2.w + x3.w);
    }
    for (; j < e; j++) {
        int s = ia[j];
        float4 x = __ldg((const float4*)(tb + (size_t)s * 64 + c));
        if (LAYER && half) x = relu_add(x, qb);
        acc.x += x.x; acc.y += x.y; acc.z += x.z; acc.w += x.w;
    }
    float inv = 1.f / fmaxf((float)(e - b), 1.f);
    *(float4*)(g_hneigh + (size_t)w * 128 + half * 64 + c) =
        make_float4(acc.x * inv, acc.y * inv, acc.z * inv, acc.w * inv);
}

// ------- fused node apply + edge-weight halves ------------------------------
// Phase A: out = relu([hn | hneigh] @ wa + ba)   (weights in 48 KB smem)
// Phase B: reload we into same smem; P = out@we[0:64], Q = out@we[64:128]
__global__ __launch_bounds__(256) void k_apply_pq(const float* __restrict__ hn,
                                                  const float* __restrict__ wa,
                                                  const float* __restrict__ ba,
                                                  const float* __restrict__ we,
                                                  float* __restrict__ out,
                                                  float* __restrict__ P,
                                                  float* __restrict__ Q) {
    __shared__ __align__(16) float s_w[192 * 64];  // 48 KB
    const int tid = threadIdx.x;
    for (int i = tid * 4; i < 192 * 64; i += 1024)
        *(float4*)(s_w + i) = *(const float4*)(wa + i);
    __syncthreads();

    const int v = blockIdx.x * 256 + tid;
    const bool act = v < NN;

    // ---- phase A: apply ----
    unsigned long long yacc[32];
#pragma unroll
    for (int m = 0; m < 16; m++) {
        float4 bb = *(const float4*)(ba + m * 4);
        yacc[2 * m]     = pack2(bb.x, bb.y);
        yacc[2 * m + 1] = pack2(bb.z, bb.w);
    }
    const float* xn = hn + (size_t)(act ? v : 0) * 64;
    const float* xg = g_hneigh + (size_t)(act ? v : 0) * 128;

    for (int ch = 0; ch < 24; ch++) {
        float4 a = make_float4(0.f, 0.f, 0.f, 0.f), d = a;
        if (act) {
            const float* p = (ch < 8) ? (xn + ch * 8) : (xg + (ch - 8) * 8);
            a = *(const float4*)p;
            d = *(const float4*)(p + 4);
        }
        float xs[8] = {a.x, a.y, a.z, a.w, d.x, d.y, d.z, d.w};
#pragma unroll
        for (int kk = 0; kk < 8; kk++) {
            unsigned long long xx = pack2(xs[kk], xs[kk]);
            const ulonglong2* wrow = (const ulonglong2*)(s_w + (ch * 8 + kk) * 64);
#pragma unroll
            for (int jj = 0; jj < 16; jj++) {
                ulonglong2 ww = wrow[jj];
                fma2(yacc[2 * jj], xx, ww.x);
                fma2(yacc[2 * jj + 1], xx, ww.y);
            }
        }
    }
    if (act) {
        float* o = out + (size_t)v * 64;
#pragma unroll
        for (int m = 0; m < 16; m++) {
            float2 f0 = unpack2(yacc[2 * m]);
            float2 f1 = unpack2(yacc[2 * m + 1]);
            *(float4*)(o + m * 4) = make_float4(fmaxf(f0.x, 0.f), fmaxf(f0.y, 0.f),
                                                fmaxf(f1.x, 0.f), fmaxf(f1.y, 0.f));
        }
    }
    __syncthreads();

    // ---- phase B: P/Q from own freshly-written row ----
    for (int i = tid * 4; i < 128 * 64; i += 1024)
        *(float4*)(s_w + i) = *(const float4*)(we + i);
    __syncthreads();

    const float* yr = out + (size_t)(act ? v : 0) * 64;
    for (int pass = 0; pass < 2; pass++) {
        unsigned long long acc[32];
#pragma unroll
        for (int jj = 0; jj < 32; jj++) acc[jj] = 0ull;
        const float* wbase = s_w + pass * 64 * 64;
        for (int k0 = 0; k0 < 16; k0++) {
            float4 f = act ? *(const float4*)(yr + k0 * 4)
                           : make_float4(0.f, 0.f, 0.f, 0.f);
            float xs[4] = {f.x, f.y, f.z, f.w};
#pragma unroll
            for (int kk = 0; kk < 4; kk++) {
                unsigned long long xx = pack2(xs[kk], xs[kk]);
                const ulonglong2* wrow = (const ulonglong2*)(wbase + (k0 * 4 + kk) * 64);
#pragma unroll
                for (int jj = 0; jj < 16; jj++) {
                    ulonglong2 ww = wrow[jj];
                    fma2(acc[2 * jj], xx, ww.x);
                    fma2(acc[2 * jj + 1], xx, ww.y);
                }
            }
        }
        if (act) {
            float* o = (pass ? Q : P) + (size_t)v * 64;
#pragma unroll
            for (int m = 0; m < 16; m++) {
                float2 f0 = unpack2(acc[2 * m]);
                float2 f1 = unpack2(acc[2 * m + 1]);
                *(float4*)(o + m * 4) = make_float4(f0.x, f0.y, f1.x, f1.y);
            }
        }
    }
}

// ---------------- final edge output: relu(P[src] + Q[dst] + be) -------------
__global__ __launch_bounds__(256) void k_edge(const int* __restrict__ src,
                                              const int* __restrict__ dst,
                                              const float* __restrict__ P,
                                              const float* __restrict__ Q,
                                              const float* __restrict__ be,
                                              float* __restrict__ oute) {
    long long g = (long long)blockIdx.x * 256 + threadIdx.x;
    int e = (int)(g >> 4);
    if (e >= NE) return;
    int c = ((int)g & 15) << 2;
    int s = __ldg(src + e), d = __ldg(dst + e);
    float4 p = __ldg((const float4*)(P + (size_t)s * 64 + c));
    float4 q = __ldg((const float4*)(Q + (size_t)d * 64 + c));
    float4 b = *(const float4*)(be + c);
    float4 r = make_float4(fmaxf(p.x + q.x + b.x, 0.f), fmaxf(p.y + q.y + b.y, 0.f),
                           fmaxf(p.z + q.z + b.z, 0.f), fmaxf(p.w + q.w + b.w, 0.f));
    __stcs((float4*)(oute + (size_t)e * 64 + c), r);   // streaming: don't evict P/Q
}

// ---------------- launch ----------------
extern "C" void kernel_launch(void* const* d_in, const int* in_sizes, int n_in,
                              void* d_out, int out_size) {
    const float* nf  = (const float*)d_in[0];
    const float* ef  = (const float*)d_in[1];
    const int*   src = (const int*)d_in[2];
    const int*   dst = (const int*)d_in[3];
    const float* wa0 = (const float*)d_in[4];
    const float* ba0 = (const float*)d_in[5];
    const float* we0 = (const float*)d_in[6];
    const float* be0 = (const float*)d_in[7];
    const float* wa1 = (const float*)d_in[8];
    const float* ba1 = (const float*)d_in[9];
    const float* we1 = (const float*)d_in[10];
    const float* be1 = (const float*)d_in[11];

    float* out_n = (float*)d_out;                       // [NN, 64]
    float* out_e = out_n + (size_t)NN * DD;             // [NE, 64]

    float *hn1, *P, *Q;
    cudaGetSymbolAddress((void**)&hn1, g_hn1);
    cudaGetSymbolAddress((void**)&P, g_P);
    cudaGetSymbolAddress((void**)&Q, g_Q);

    // CSR build (graph shared by both layers)
    k_zero<<<(NN + 255) / 256, 256>>>();
    k_count<<<(NE + 255) / 256, 256>>>(dst);
    k_scan<<<1, 1024>>>();
    k_fill<<<(NE + 255) / 256, 256>>>(src, dst);

    // layer 1
    k_agg<0><<<(NN + 7) / 8, 256>>>(nf, ef, nullptr, nullptr, nullptr);
    k_apply_pq<<<(NN + 255) / 256, 256>>>(nf, wa0, ba0, we0, hn1, P, Q);

    // layer 2 (h_e1 never materialized: recomputed inside k_agg)
    k_agg<1><<<(NN + 7) / 8, 256>>>(hn1, nullptr, P, Q, be0);
    k_apply_pq<<<(NN + 255) / 256, 256>>>(hn1, wa1, ba1, we1, out_n, P, Q);

    // final edge features straight into d_out
    k_edge<<<((long long)NE * 16 + 255) / 256, 256>>>(src, dst, P, Q, be1, out_e);
}